// round 1
// baseline (speedup 1.0000x reference)
#include <cuda_runtime.h>
#include <cstdint>

// Problem constants (shape-fixed by the dataset); capacities for device scratch.
#define MAXN 50000
#define MAXE 800000

// Device scratch (allocation-free rule: __device__ globals)
__device__ float g_diag[(size_t)MAXN * 16];          // per-node Gram accumulators
__device__ float g_invs[(size_t)MAXN * 16];          // per-node inverse sqrt matrices
__device__ float g_triu[(size_t)MAXE * 16];          // per-edge M1^T M2

// ---------------------------------------------------------------------------
// Kernel 0: zero the diag accumulators (float4 grid)
// ---------------------------------------------------------------------------
__global__ void k_zero_diag(int n4) {
    int i = blockIdx.x * blockDim.x + threadIdx.x;
    if (i < n4) reinterpret_cast<float4*>(g_diag)[i] = make_float4(0.f, 0.f, 0.f, 0.f);
}

// ---------------------------------------------------------------------------
// Kernel 1: per edge-pair e in [0,E):
//   M1 = maps[e], M2 = maps[E+e]
//   atomically add M1^T M1 into diag[row[e]], M2^T M2 into diag[col[e]]
//   store P = M1^T M2 into g_triu[e]
// row[e] = edge_index[0][e], col[e] = edge_index[0][E+e]
// ---------------------------------------------------------------------------
__global__ void k_edges(const float* __restrict__ maps,
                        const int*   __restrict__ ei0,
                        int E) {
    int e = blockIdx.x * blockDim.x + threadIdx.x;
    if (e >= E) return;

    const float4* mp = reinterpret_cast<const float4*>(maps);
    float m1[4][4], m2[4][4];
#pragma unroll
    for (int k = 0; k < 4; k++) {
        float4 a = mp[(size_t)e * 4 + k];
        float4 b = mp[((size_t)E + e) * 4 + k];
        m1[k][0] = a.x; m1[k][1] = a.y; m1[k][2] = a.z; m1[k][3] = a.w;
        m2[k][0] = b.x; m2[k][1] = b.y; m2[k][2] = b.z; m2[k][3] = b.w;
    }

    float C1[16], C2[16], P[16];
#pragma unroll
    for (int i = 0; i < 4; i++) {
#pragma unroll
        for (int j = 0; j < 4; j++) {
            float s1 = 0.f, s2 = 0.f, sp = 0.f;
#pragma unroll
            for (int k = 0; k < 4; k++) {
                s1 += m1[k][i] * m1[k][j];
                s2 += m2[k][i] * m2[k][j];
                sp += m1[k][i] * m2[k][j];
            }
            C1[i * 4 + j] = s1; C2[i * 4 + j] = s2; P[i * 4 + j] = sp;
        }
    }

    int r = ei0[e];
    int c = ei0[E + e];

    float4* dr = reinterpret_cast<float4*>(&g_diag[(size_t)r * 16]);
    float4* dc = reinterpret_cast<float4*>(&g_diag[(size_t)c * 16]);
    float4* tp = reinterpret_cast<float4*>(&g_triu[(size_t)e * 16]);
#pragma unroll
    for (int q = 0; q < 4; q++) {
        atomicAdd(&dr[q], *reinterpret_cast<float4*>(&C1[q * 4]));   // sm_90+ vector RED
        atomicAdd(&dc[q], *reinterpret_cast<float4*>(&C2[q * 4]));
        tp[q] = *reinterpret_cast<float4*>(&P[q * 4]);
    }
}

// 4x4 matmul helper: C = A * B (row-major [16])
__device__ __forceinline__ void mm4(const float* __restrict__ A,
                                    const float* __restrict__ B,
                                    float* __restrict__ C) {
#pragma unroll
    for (int i = 0; i < 4; i++) {
#pragma unroll
        for (int j = 0; j < 4; j++) {
            float s = A[i * 4 + 0] * B[0 * 4 + j];
            s += A[i * 4 + 1] * B[1 * 4 + j];
            s += A[i * 4 + 2] * B[2 * 4 + j];
            s += A[i * 4 + 3] * B[3 * 4 + j];
            C[i * 4 + j] = s;
        }
    }
}

// ---------------------------------------------------------------------------
// Kernel 2: per node n:
//   A = diag[n] + I  (SPD, evals >= 1)
//   Z = A^{-1/2} via coupled Newton-Schulz (Denman-Beavers Y/Z form)
//   store Z; emit diag block of output: rows, cols, vals = clip(Z*diag*Z)
// ---------------------------------------------------------------------------
__global__ void k_nodes(float* __restrict__ out, int N, long long L) {
    int n = blockIdx.x * blockDim.x + threadIdx.x;
    if (n >= N) return;

    float A0[16], A[16];
    const float4* dp = reinterpret_cast<const float4*>(&g_diag[(size_t)n * 16]);
#pragma unroll
    for (int q = 0; q < 4; q++) {
        float4 v = dp[q];
        A0[q * 4 + 0] = v.x; A0[q * 4 + 1] = v.y; A0[q * 4 + 2] = v.z; A0[q * 4 + 3] = v.w;
    }
#pragma unroll
    for (int i = 0; i < 16; i++) A[i] = A0[i];
    A[0] += 1.f; A[5] += 1.f; A[10] += 1.f; A[15] += 1.f;

    // spectral upper bound: min(trace, Gershgorin inf-norm)
    float tr = A[0] + A[5] + A[10] + A[15];
    float g = 0.f;
#pragma unroll
    for (int i = 0; i < 4; i++) {
        float rs = fabsf(A[i * 4 + 0]) + fabsf(A[i * 4 + 1]) +
                   fabsf(A[i * 4 + 2]) + fabsf(A[i * 4 + 3]);
        g = fmaxf(g, rs);
    }
    float s = fminf(tr, g);
    float inv_s = 1.f / s;

    float Y[16], Z[16];
#pragma unroll
    for (int i = 0; i < 16; i++) { Y[i] = A[i] * inv_s; Z[i] = 0.f; }
    Z[0] = Z[5] = Z[10] = Z[15] = 1.f;

#pragma unroll
    for (int it = 0; it < 14; it++) {
        float T[16], Yn[16], Zn[16];
        mm4(Z, Y, T);
#pragma unroll
        for (int i = 0; i < 16; i++) T[i] = -0.5f * T[i];
        T[0] += 1.5f; T[5] += 1.5f; T[10] += 1.5f; T[15] += 1.5f;
        mm4(Y, T, Yn);
        mm4(T, Z, Zn);
#pragma unroll
        for (int i = 0; i < 16; i++) { Y[i] = Yn[i]; Z[i] = Zn[i]; }
    }

    float rs = rsqrtf(s);
#pragma unroll
    for (int i = 0; i < 16; i++) Z[i] *= rs;      // Z = (diag+I)^{-1/2}

    float4* zp = reinterpret_cast<float4*>(&g_invs[(size_t)n * 16]);
#pragma unroll
    for (int q = 0; q < 4; q++)
        zp[q] = *reinterpret_cast<float4*>(&Z[q * 4]);

    // D = clip(Z * A0 * Z)
    float W[16], Dm[16];
    mm4(Z, A0, W);
    mm4(W, Z, Dm);
#pragma unroll
    for (int i = 0; i < 16; i++) Dm[i] = fminf(fmaxf(Dm[i], -1.f), 1.f);

    size_t base = (size_t)n * 16;
    float4* orow = reinterpret_cast<float4*>(out + base);
    float4* ocol = reinterpret_cast<float4*>(out + (size_t)L + base);
    float4* oval = reinterpret_cast<float4*>(out + 2 * (size_t)L + base);
    float nb = (float)(n * 4);
    float4 cv = make_float4(nb, nb + 1.f, nb + 2.f, nb + 3.f);
#pragma unroll
    for (int a = 0; a < 4; a++) {
        float rv = nb + (float)a;
        orow[a] = make_float4(rv, rv, rv, rv);
        ocol[a] = cv;
        oval[a] = *reinterpret_cast<float4*>(&Dm[a * 4]);
    }
}

// ---------------------------------------------------------------------------
// Kernel 3: per edge e:
//   T = clip(Z[row] * P * Z[col]); emit ij block (-T) and ji block (-T^T)
// ---------------------------------------------------------------------------
__global__ void k_out(float* __restrict__ out,
                      const int* __restrict__ ei0,
                      int E, int N, long long L) {
    int e = blockIdx.x * blockDim.x + threadIdx.x;
    if (e >= E) return;

    float P[16], Zi[16], Zj[16];
    const float4* tp = reinterpret_cast<const float4*>(&g_triu[(size_t)e * 16]);
#pragma unroll
    for (int q = 0; q < 4; q++) {
        float4 v = tp[q];
        P[q * 4 + 0] = v.x; P[q * 4 + 1] = v.y; P[q * 4 + 2] = v.z; P[q * 4 + 3] = v.w;
    }
    int r = ei0[e];
    int c = ei0[E + e];
    const float4* zi = reinterpret_cast<const float4*>(&g_invs[(size_t)r * 16]);
    const float4* zj = reinterpret_cast<const float4*>(&g_invs[(size_t)c * 16]);
#pragma unroll
    for (int q = 0; q < 4; q++) {
        float4 a = zi[q], b = zj[q];
        Zi[q * 4 + 0] = a.x; Zi[q * 4 + 1] = a.y; Zi[q * 4 + 2] = a.z; Zi[q * 4 + 3] = a.w;
        Zj[q * 4 + 0] = b.x; Zj[q * 4 + 1] = b.y; Zj[q * 4 + 2] = b.z; Zj[q * 4 + 3] = b.w;
    }

    float W[16], T[16];
    mm4(Zi, P, W);
    mm4(W, Zj, T);
#pragma unroll
    for (int i = 0; i < 16; i++) T[i] = fminf(fmaxf(T[i], -1.f), 1.f);

    size_t N16 = (size_t)N * 16;
    size_t E16 = (size_t)E * 16;
    size_t bij = N16 + (size_t)e * 16;
    size_t bji = N16 + E16 + (size_t)e * 16;

    float4* rij = reinterpret_cast<float4*>(out + bij);
    float4* rji = reinterpret_cast<float4*>(out + bji);
    float4* cij = reinterpret_cast<float4*>(out + (size_t)L + bij);
    float4* cji = reinterpret_cast<float4*>(out + (size_t)L + bji);
    float4* vij = reinterpret_cast<float4*>(out + 2 * (size_t)L + bij);
    float4* vji = reinterpret_cast<float4*>(out + 2 * (size_t)L + bji);

    float rb = (float)(r * 4);
    float cb = (float)(c * 4);
    float4 rseq = make_float4(rb, rb + 1.f, rb + 2.f, rb + 3.f);
    float4 cseq = make_float4(cb, cb + 1.f, cb + 2.f, cb + 3.f);
#pragma unroll
    for (int a = 0; a < 4; a++) {
        float rv = rb + (float)a;
        float cv = cb + (float)a;
        rij[a] = make_float4(rv, rv, rv, rv);   // rows ij: row[e]*4 + a
        rji[a] = make_float4(cv, cv, cv, cv);   // rows ji: col[e]*4 + a
        cij[a] = cseq;                          // cols ij: col[e]*4 + b
        cji[a] = rseq;                          // cols ji: row[e]*4 + b
        vij[a] = make_float4(-T[a * 4 + 0], -T[a * 4 + 1], -T[a * 4 + 2], -T[a * 4 + 3]);
        vji[a] = make_float4(-T[0 * 4 + a], -T[1 * 4 + a], -T[2 * 4 + a], -T[3 * 4 + a]);
    }
}

// ---------------------------------------------------------------------------
extern "C" void kernel_launch(void* const* d_in, const int* in_sizes, int n_in,
                              void* d_out, int out_size) {
    const float* maps = (const float*)d_in[0];
    const int*   ei   = (const int*)d_in[1];
    float*       out  = (float*)d_out;

    int twoE = in_sizes[0] / 16;           // 2E
    int E    = twoE / 2;
    long long L = (long long)out_size / 3; // entries per index array
    int N = (int)(L / 16 - twoE);          // N = L/16 - 2E

    int n4 = N * 4;  // float4 count of g_diag region
    k_zero_diag<<<(n4 + 255) / 256, 256>>>(n4);
    k_edges<<<(E + 127) / 128, 128>>>(maps, ei, E);
    k_nodes<<<(N + 127) / 128, 128>>>(out, N, L);
    k_out<<<(E + 127) / 128, 128>>>(out, ei, E, N, L);
}

// round 2
// speedup vs baseline: 1.4267x; 1.4267x over previous
#include <cuda_runtime.h>
#include <cstdint>

#define MAXN 50000
#define MAXE 800000

// Device scratch (allocation-free rule: __device__ globals)
__device__ float g_diag[(size_t)MAXN * 16];   // per-node Gram accumulators
__device__ float g_invs[(size_t)MAXN * 16];   // per-node inverse sqrt matrices
__device__ float g_triu[(size_t)MAXE * 16];   // per-edge M1^T M2

// float4 helpers
__device__ __forceinline__ float4 f4_fma(float s, float4 v, float4 acc) {
    acc.x = fmaf(s, v.x, acc.x); acc.y = fmaf(s, v.y, acc.y);
    acc.z = fmaf(s, v.z, acc.z); acc.w = fmaf(s, v.w, acc.w);
    return acc;
}
__device__ __forceinline__ float4 f4_scale(float s, float4 v) {
    return make_float4(s * v.x, s * v.y, s * v.z, s * v.w);
}
__device__ __forceinline__ float f4_dot(float4 a, float4 b) {
    return fmaf(a.x, b.x, fmaf(a.y, b.y, fmaf(a.z, b.z, a.w * b.w)));
}
__device__ __forceinline__ float pick(float4 v, int a) {
    float r = v.x;
    r = (a == 1) ? v.y : r;
    r = (a == 2) ? v.z : r;
    r = (a == 3) ? v.w : r;
    return r;
}
__device__ __forceinline__ float4 pick4(float4 v0, float4 v1, float4 v2, float4 v3, int a) {
    float4 r = v0;
    r = (a == 1) ? v1 : r;
    r = (a == 2) ? v2 : r;
    r = (a == 3) ? v3 : r;
    return r;
}
__device__ __forceinline__ float4 clipneg(float4 v) {
    return make_float4(-fminf(fmaxf(v.x, -1.f), 1.f),
                       -fminf(fmaxf(v.y, -1.f), 1.f),
                       -fminf(fmaxf(v.z, -1.f), 1.f),
                       -fminf(fmaxf(v.w, -1.f), 1.f));
}

// ---------------------------------------------------------------------------
// Kernel 0: zero the diag accumulators
// ---------------------------------------------------------------------------
__global__ void k_zero_diag(int n4) {
    int i = blockIdx.x * blockDim.x + threadIdx.x;
    if (i < n4) reinterpret_cast<float4*>(g_diag)[i] = make_float4(0.f, 0.f, 0.f, 0.f);
}

// ---------------------------------------------------------------------------
// Kernel 1 (quad-per-edge): thread (e, a) computes row a of
//   C1 = M1^T M1  -> atomicAdd into diag[row]
//   C2 = M2^T M2  -> atomicAdd into diag[col]
//   P  = M1^T M2  -> store g_triu[e] row a
// Row a of M^T X = (column a of M) dotted against rows of X.
// ---------------------------------------------------------------------------
__global__ void k_edges(const float* __restrict__ maps,
                        const int*   __restrict__ ei0,
                        int E) {
    int t = blockIdx.x * blockDim.x + threadIdx.x;
    int e = t >> 2, a = t & 3;
    if (e >= E) return;

    const float4* mp = reinterpret_cast<const float4*>(maps);
    float4 m10 = mp[(size_t)e * 4 + 0];
    float4 m11 = mp[(size_t)e * 4 + 1];
    float4 m12 = mp[(size_t)e * 4 + 2];
    float4 m13 = mp[(size_t)e * 4 + 3];
    float4 m20 = mp[((size_t)E + e) * 4 + 0];
    float4 m21 = mp[((size_t)E + e) * 4 + 1];
    float4 m22 = mp[((size_t)E + e) * 4 + 2];
    float4 m23 = mp[((size_t)E + e) * 4 + 3];

    // column a of m1, m2
    float a10 = pick(m10, a), a11 = pick(m11, a), a12 = pick(m12, a), a13 = pick(m13, a);
    float a20 = pick(m20, a), a21 = pick(m21, a), a22 = pick(m22, a), a23 = pick(m23, a);

    float4 z = make_float4(0.f, 0.f, 0.f, 0.f);
    float4 c1 = f4_fma(a13, m13, f4_fma(a12, m12, f4_fma(a11, m11, f4_fma(a10, m10, z))));
    float4 c2 = f4_fma(a23, m23, f4_fma(a22, m22, f4_fma(a21, m21, f4_fma(a20, m20, z))));
    float4 p  = f4_fma(a13, m23, f4_fma(a12, m22, f4_fma(a11, m21, f4_fma(a10, m20, z))));

    int r = ei0[e];
    int c = ei0[E + e];

    atomicAdd(reinterpret_cast<float4*>(g_diag) + (size_t)r * 4 + a, c1);
    atomicAdd(reinterpret_cast<float4*>(g_diag) + (size_t)c * 4 + a, c2);
    reinterpret_cast<float4*>(g_triu)[(size_t)e * 4 + a] = p;
}

// 4x4 matmul helper (row-major [16])
__device__ __forceinline__ void mm4(const float* __restrict__ A,
                                    const float* __restrict__ B,
                                    float* __restrict__ C) {
#pragma unroll
    for (int i = 0; i < 4; i++) {
#pragma unroll
        for (int j = 0; j < 4; j++) {
            float s = A[i * 4 + 0] * B[0 * 4 + j];
            s += A[i * 4 + 1] * B[1 * 4 + j];
            s += A[i * 4 + 2] * B[2 * 4 + j];
            s += A[i * 4 + 3] * B[3 * 4 + j];
            C[i * 4 + j] = s;
        }
    }
}

// ---------------------------------------------------------------------------
// Kernel 2: per node n: Z = (diag+I)^{-1/2} via Newton-Schulz,
// store Z, emit diag block (rows, cols, vals).
// ---------------------------------------------------------------------------
__global__ void k_nodes(float* __restrict__ out, int N, long long L) {
    int n = blockIdx.x * blockDim.x + threadIdx.x;
    if (n >= N) return;

    float A0[16], A[16];
    const float4* dp = reinterpret_cast<const float4*>(&g_diag[(size_t)n * 16]);
#pragma unroll
    for (int q = 0; q < 4; q++) {
        float4 v = dp[q];
        A0[q * 4 + 0] = v.x; A0[q * 4 + 1] = v.y; A0[q * 4 + 2] = v.z; A0[q * 4 + 3] = v.w;
    }
#pragma unroll
    for (int i = 0; i < 16; i++) A[i] = A0[i];
    A[0] += 1.f; A[5] += 1.f; A[10] += 1.f; A[15] += 1.f;

    float tr = A[0] + A[5] + A[10] + A[15];
    float g = 0.f;
#pragma unroll
    for (int i = 0; i < 4; i++) {
        float rs = fabsf(A[i * 4 + 0]) + fabsf(A[i * 4 + 1]) +
                   fabsf(A[i * 4 + 2]) + fabsf(A[i * 4 + 3]);
        g = fmaxf(g, rs);
    }
    float s = fminf(tr, g);
    float inv_s = 1.f / s;

    float Y[16], Z[16];
#pragma unroll
    for (int i = 0; i < 16; i++) { Y[i] = A[i] * inv_s; Z[i] = 0.f; }
    Z[0] = Z[5] = Z[10] = Z[15] = 1.f;

#pragma unroll
    for (int it = 0; it < 14; it++) {
        float T[16], Yn[16], Zn[16];
        mm4(Z, Y, T);
#pragma unroll
        for (int i = 0; i < 16; i++) T[i] = -0.5f * T[i];
        T[0] += 1.5f; T[5] += 1.5f; T[10] += 1.5f; T[15] += 1.5f;
        mm4(Y, T, Yn);
        mm4(T, Z, Zn);
#pragma unroll
        for (int i = 0; i < 16; i++) { Y[i] = Yn[i]; Z[i] = Zn[i]; }
    }

    float rs = rsqrtf(s);
#pragma unroll
    for (int i = 0; i < 16; i++) Z[i] *= rs;

    float4* zp = reinterpret_cast<float4*>(&g_invs[(size_t)n * 16]);
#pragma unroll
    for (int q = 0; q < 4; q++)
        zp[q] = *reinterpret_cast<float4*>(&Z[q * 4]);

    float W[16], Dm[16];
    mm4(Z, A0, W);
    mm4(W, Z, Dm);
#pragma unroll
    for (int i = 0; i < 16; i++) Dm[i] = fminf(fmaxf(Dm[i], -1.f), 1.f);

    size_t base = (size_t)n * 16;
    float4* orow = reinterpret_cast<float4*>(out + base);
    float4* ocol = reinterpret_cast<float4*>(out + (size_t)L + base);
    float4* oval = reinterpret_cast<float4*>(out + 2 * (size_t)L + base);
    float nb = (float)(n * 4);
    float4 cv = make_float4(nb, nb + 1.f, nb + 2.f, nb + 3.f);
#pragma unroll
    for (int a = 0; a < 4; a++) {
        float rv = nb + (float)a;
        orow[a] = make_float4(rv, rv, rv, rv);
        ocol[a] = cv;
        oval[a] = *reinterpret_cast<float4*>(&Dm[a * 4]);
    }
}

// ---------------------------------------------------------------------------
// Kernel 3 (pure streaming): edge-block indices. Thread (e, a) writes 4
// fully-coalesced float4s (rows_ij, cols_ij, rows_ji, cols_ji).
// ---------------------------------------------------------------------------
__global__ void k_idx(float* __restrict__ out,
                      const int* __restrict__ ei0,
                      int E, int N, long long L) {
    int t = blockIdx.x * blockDim.x + threadIdx.x;
    int e = t >> 2, a = t & 3;
    if (e >= E) return;

    int r = ei0[e];
    int c = ei0[E + e];

    float4* o = reinterpret_cast<float4*>(out);
    size_t L4 = (size_t)L >> 2;
    size_t ij = (size_t)N * 4 + (size_t)e * 4 + a;
    size_t ji = ij + (size_t)E * 4;

    float rb = (float)(r * 4);
    float cb = (float)(c * 4);
    float ra = rb + (float)a;
    float ca = cb + (float)a;

    o[ij]      = make_float4(ra, ra, ra, ra);                    // rows ij
    o[L4 + ij] = make_float4(cb, cb + 1.f, cb + 2.f, cb + 3.f);  // cols ij
    o[ji]      = make_float4(ca, ca, ca, ca);                    // rows ji
    o[L4 + ji] = make_float4(rb, rb + 1.f, rb + 2.f, rb + 3.f);  // cols ji
}

// ---------------------------------------------------------------------------
// Kernel 4 (quad-per-edge): thread (e, a) computes row a of
//   T  = Zi * P * Zj   (clip)   -> vals ij = -T row a
//   T^T row a = col a of T = Zi * (P * Zj[:,a]); Zj symmetric so
//   Zj[:,a] = Zj row a.                        -> vals ji = -T^T row a
// ---------------------------------------------------------------------------
__global__ void k_vals(float* __restrict__ out,
                       const int* __restrict__ ei0,
                       int E, int N, long long L) {
    int t = blockIdx.x * blockDim.x + threadIdx.x;
    int e = t >> 2, a = t & 3;
    if (e >= E) return;

    const float4* tp = reinterpret_cast<const float4*>(g_triu) + (size_t)e * 4;
    float4 P0 = tp[0], P1 = tp[1], P2 = tp[2], P3 = tp[3];

    int r = ei0[e];
    int c = ei0[E + e];

    const float4* zi = reinterpret_cast<const float4*>(g_invs) + (size_t)r * 4;
    const float4* zj = reinterpret_cast<const float4*>(g_invs) + (size_t)c * 4;
    float4 Zi0 = zi[0], Zi1 = zi[1], Zi2 = zi[2], Zi3 = zi[3];
    float4 Zj0 = zj[0], Zj1 = zj[1], Zj2 = zj[2], Zj3 = zj[3];

    float4 zia = pick4(Zi0, Zi1, Zi2, Zi3, a);
    float4 zja = pick4(Zj0, Zj1, Zj2, Zj3, a);

    // w = Zi[a,:] * P
    float4 z0 = make_float4(0.f, 0.f, 0.f, 0.f);
    float4 w = f4_fma(zia.w, P3, f4_fma(zia.z, P2, f4_fma(zia.y, P1, f4_fma(zia.x, P0, z0))));
    // T row a = w * Zj
    float4 trow = f4_fma(w.w, Zj3, f4_fma(w.z, Zj2, f4_fma(w.y, Zj1, f4_fma(w.x, Zj0, z0))));
    // u = P * Zj[:,a] (= P * Zj row a, symmetry)
    float4 u = make_float4(f4_dot(P0, zja), f4_dot(P1, zja), f4_dot(P2, zja), f4_dot(P3, zja));
    // T^T row a = Zi * u
    float4 tcol = make_float4(f4_dot(Zi0, u), f4_dot(Zi1, u), f4_dot(Zi2, u), f4_dot(Zi3, u));

    float4* o = reinterpret_cast<float4*>(out);
    size_t L4 = (size_t)L >> 2;
    size_t ij = 2 * L4 + (size_t)N * 4 + (size_t)e * 4 + a;
    size_t ji = ij + (size_t)E * 4;

    o[ij] = clipneg(trow);
    o[ji] = clipneg(tcol);
}

// ---------------------------------------------------------------------------
extern "C" void kernel_launch(void* const* d_in, const int* in_sizes, int n_in,
                              void* d_out, int out_size) {
    const float* maps = (const float*)d_in[0];
    const int*   ei   = (const int*)d_in[1];
    float*       out  = (float*)d_out;

    int twoE = in_sizes[0] / 16;           // 2E
    int E    = twoE / 2;
    long long L = (long long)out_size / 3; // entries per index array
    int N = (int)(L / 16 - twoE);

    int n4 = N * 4;
    int qe = E * 4;
    k_zero_diag<<<(n4 + 255) / 256, 256>>>(n4);
    k_edges<<<(qe + 255) / 256, 256>>>(maps, ei, E);
    k_nodes<<<(N + 127) / 128, 128>>>(out, N, L);
    k_idx  <<<(qe + 255) / 256, 256>>>(out, ei, E, N, L);
    k_vals <<<(qe + 255) / 256, 256>>>(out, ei, E, N, L);
}

// round 3
// speedup vs baseline: 1.6982x; 1.1903x over previous
#include <cuda_runtime.h>
#include <cstdint>

#define MAXN 50000
#define MAXE 800000

// Device scratch (allocation-free rule: __device__ globals)
__device__ float g_diag[(size_t)MAXN * 16];   // per-node Gram accumulators
__device__ float g_invs[(size_t)MAXN * 16];   // per-node inverse sqrt matrices
__device__ float g_triu[(size_t)MAXE * 16];   // per-edge M1^T M2

// float4 helpers
__device__ __forceinline__ float4 f4_fma(float s, float4 v, float4 acc) {
    acc.x = fmaf(s, v.x, acc.x); acc.y = fmaf(s, v.y, acc.y);
    acc.z = fmaf(s, v.z, acc.z); acc.w = fmaf(s, v.w, acc.w);
    return acc;
}
__device__ __forceinline__ float f4_dot(float4 a, float4 b) {
    return fmaf(a.x, b.x, fmaf(a.y, b.y, fmaf(a.z, b.z, a.w * b.w)));
}
__device__ __forceinline__ float pick(float4 v, int a) {
    float r = v.x;
    r = (a == 1) ? v.y : r;
    r = (a == 2) ? v.z : r;
    r = (a == 3) ? v.w : r;
    return r;
}
__device__ __forceinline__ float4 pick4(float4 v0, float4 v1, float4 v2, float4 v3, int a) {
    float4 r = v0;
    r = (a == 1) ? v1 : r;
    r = (a == 2) ? v2 : r;
    r = (a == 3) ? v3 : r;
    return r;
}
__device__ __forceinline__ float4 clipneg(float4 v) {
    return make_float4(-fminf(fmaxf(v.x, -1.f), 1.f),
                       -fminf(fmaxf(v.y, -1.f), 1.f),
                       -fminf(fmaxf(v.z, -1.f), 1.f),
                       -fminf(fmaxf(v.w, -1.f), 1.f));
}

// ---------------------------------------------------------------------------
// Kernel 0: zero the diag accumulators
// ---------------------------------------------------------------------------
__global__ void k_zero_diag(int n4) {
    int i = blockIdx.x * blockDim.x + threadIdx.x;
    if (i < n4) reinterpret_cast<float4*>(g_diag)[i] = make_float4(0.f, 0.f, 0.f, 0.f);
}

// ---------------------------------------------------------------------------
// Kernel 1 (quad-per-edge): thread (e, a) computes row a of
//   C1 = M1^T M1 -> atomicAdd diag[row];  C2 = M2^T M2 -> atomicAdd diag[col]
//   P  = M1^T M2 -> streaming store g_triu[e] row a
// maps read-once (__ldcs), triu write-once (__stcs).
// ---------------------------------------------------------------------------
__global__ void k_edges(const float* __restrict__ maps,
                        const int*   __restrict__ ei0,
                        int E) {
    int t = blockIdx.x * blockDim.x + threadIdx.x;
    int e = t >> 2, a = t & 3;
    if (e >= E) return;

    const float4* mp = reinterpret_cast<const float4*>(maps);
    float4 m10 = __ldcs(mp + (size_t)e * 4 + 0);
    float4 m11 = __ldcs(mp + (size_t)e * 4 + 1);
    float4 m12 = __ldcs(mp + (size_t)e * 4 + 2);
    float4 m13 = __ldcs(mp + (size_t)e * 4 + 3);
    float4 m20 = __ldcs(mp + ((size_t)E + e) * 4 + 0);
    float4 m21 = __ldcs(mp + ((size_t)E + e) * 4 + 1);
    float4 m22 = __ldcs(mp + ((size_t)E + e) * 4 + 2);
    float4 m23 = __ldcs(mp + ((size_t)E + e) * 4 + 3);

    // column a of m1, m2
    float a10 = pick(m10, a), a11 = pick(m11, a), a12 = pick(m12, a), a13 = pick(m13, a);
    float a20 = pick(m20, a), a21 = pick(m21, a), a22 = pick(m22, a), a23 = pick(m23, a);

    float4 z = make_float4(0.f, 0.f, 0.f, 0.f);
    float4 c1 = f4_fma(a13, m13, f4_fma(a12, m12, f4_fma(a11, m11, f4_fma(a10, m10, z))));
    float4 c2 = f4_fma(a23, m23, f4_fma(a22, m22, f4_fma(a21, m21, f4_fma(a20, m20, z))));
    float4 p  = f4_fma(a13, m23, f4_fma(a12, m22, f4_fma(a11, m21, f4_fma(a10, m20, z))));

    int r = ei0[e];
    int c = ei0[E + e];

    atomicAdd(reinterpret_cast<float4*>(g_diag) + (size_t)r * 4 + a, c1);
    atomicAdd(reinterpret_cast<float4*>(g_diag) + (size_t)c * 4 + a, c2);
    __stcs(reinterpret_cast<float4*>(g_triu) + (size_t)e * 4 + a, p);
}

// 4x4 matmul helper (row-major [16])
__device__ __forceinline__ void mm4(const float* __restrict__ A,
                                    const float* __restrict__ B,
                                    float* __restrict__ C) {
#pragma unroll
    for (int i = 0; i < 4; i++) {
#pragma unroll
        for (int j = 0; j < 4; j++) {
            float s = A[i * 4 + 0] * B[0 * 4 + j];
            s += A[i * 4 + 1] * B[1 * 4 + j];
            s += A[i * 4 + 2] * B[2 * 4 + j];
            s += A[i * 4 + 3] * B[3 * 4 + j];
            C[i * 4 + j] = s;
        }
    }
}

// ---------------------------------------------------------------------------
// Kernel 2: per node n: Z = (diag+I)^{-1/2} via Newton-Schulz,
// store Z, emit diag block (rows, cols, vals).
// ---------------------------------------------------------------------------
__global__ void k_nodes(float* __restrict__ out, int N, long long L) {
    int n = blockIdx.x * blockDim.x + threadIdx.x;
    if (n >= N) return;

    float A0[16], A[16];
    const float4* dp = reinterpret_cast<const float4*>(&g_diag[(size_t)n * 16]);
#pragma unroll
    for (int q = 0; q < 4; q++) {
        float4 v = dp[q];
        A0[q * 4 + 0] = v.x; A0[q * 4 + 1] = v.y; A0[q * 4 + 2] = v.z; A0[q * 4 + 3] = v.w;
    }
#pragma unroll
    for (int i = 0; i < 16; i++) A[i] = A0[i];
    A[0] += 1.f; A[5] += 1.f; A[10] += 1.f; A[15] += 1.f;

    float tr = A[0] + A[5] + A[10] + A[15];
    float g = 0.f;
#pragma unroll
    for (int i = 0; i < 4; i++) {
        float rs = fabsf(A[i * 4 + 0]) + fabsf(A[i * 4 + 1]) +
                   fabsf(A[i * 4 + 2]) + fabsf(A[i * 4 + 3]);
        g = fmaxf(g, rs);
    }
    float s = fminf(tr, g);
    float inv_s = 1.f / s;

    float Y[16], Z[16];
#pragma unroll
    for (int i = 0; i < 16; i++) { Y[i] = A[i] * inv_s; Z[i] = 0.f; }
    Z[0] = Z[5] = Z[10] = Z[15] = 1.f;

#pragma unroll
    for (int it = 0; it < 14; it++) {
        float T[16], Yn[16], Zn[16];
        mm4(Z, Y, T);
#pragma unroll
        for (int i = 0; i < 16; i++) T[i] = -0.5f * T[i];
        T[0] += 1.5f; T[5] += 1.5f; T[10] += 1.5f; T[15] += 1.5f;
        mm4(Y, T, Yn);
        mm4(T, Z, Zn);
#pragma unroll
        for (int i = 0; i < 16; i++) { Y[i] = Yn[i]; Z[i] = Zn[i]; }
    }

    float rs = rsqrtf(s);
#pragma unroll
    for (int i = 0; i < 16; i++) Z[i] *= rs;

    float4* zp = reinterpret_cast<float4*>(&g_invs[(size_t)n * 16]);
#pragma unroll
    for (int q = 0; q < 4; q++)
        zp[q] = *reinterpret_cast<float4*>(&Z[q * 4]);

    float W[16], Dm[16];
    mm4(Z, A0, W);
    mm4(W, Z, Dm);
#pragma unroll
    for (int i = 0; i < 16; i++) Dm[i] = fminf(fmaxf(Dm[i], -1.f), 1.f);

    size_t base = (size_t)n * 16;
    float4* orow = reinterpret_cast<float4*>(out + base);
    float4* ocol = reinterpret_cast<float4*>(out + (size_t)L + base);
    float4* oval = reinterpret_cast<float4*>(out + 2 * (size_t)L + base);
    float nb = (float)(n * 4);
    float4 cv = make_float4(nb, nb + 1.f, nb + 2.f, nb + 3.f);
#pragma unroll
    for (int a = 0; a < 4; a++) {
        float rv = nb + (float)a;
        __stcs(orow + a, make_float4(rv, rv, rv, rv));
        __stcs(ocol + a, cv);
        __stcs(oval + a, *reinterpret_cast<float4*>(&Dm[a * 4]));
    }
}

// ---------------------------------------------------------------------------
// Kernel 3 (fused emit, quad-per-edge): thread (e, a) emits all six output
// float4s for its row: rows/cols/vals for the ij block and the ji block.
//   T = clip(Zi * P * Zj); vals_ij = -T row a; vals_ji = -(T^T) row a.
//   (Z symmetric: Zj[:,a] = Zj row a.)
// ---------------------------------------------------------------------------
__global__ void k_emit(float* __restrict__ out,
                       const int* __restrict__ ei0,
                       int E, int N, long long L) {
    int t = blockIdx.x * blockDim.x + threadIdx.x;
    int e = t >> 2, a = t & 3;
    if (e >= E) return;

    const float4* tp = reinterpret_cast<const float4*>(g_triu) + (size_t)e * 4;
    float4 P0 = __ldcs(tp + 0), P1 = __ldcs(tp + 1);
    float4 P2 = __ldcs(tp + 2), P3 = __ldcs(tp + 3);

    int r = ei0[e];
    int c = ei0[E + e];

    const float4* zi = reinterpret_cast<const float4*>(g_invs) + (size_t)r * 4;
    const float4* zj = reinterpret_cast<const float4*>(g_invs) + (size_t)c * 4;
    float4 Zi0 = __ldg(zi + 0), Zi1 = __ldg(zi + 1), Zi2 = __ldg(zi + 2), Zi3 = __ldg(zi + 3);
    float4 Zj0 = __ldg(zj + 0), Zj1 = __ldg(zj + 1), Zj2 = __ldg(zj + 2), Zj3 = __ldg(zj + 3);

    float4 zia = pick4(Zi0, Zi1, Zi2, Zi3, a);
    float4 zja = pick4(Zj0, Zj1, Zj2, Zj3, a);

    float4 z0 = make_float4(0.f, 0.f, 0.f, 0.f);
    // T row a = (Zi[a,:] * P) * Zj
    float4 w = f4_fma(zia.w, P3, f4_fma(zia.z, P2, f4_fma(zia.y, P1, f4_fma(zia.x, P0, z0))));
    float4 trow = f4_fma(w.w, Zj3, f4_fma(w.z, Zj2, f4_fma(w.y, Zj1, f4_fma(w.x, Zj0, z0))));
    // T^T row a = Zi * (P * Zj[:,a])
    float4 u = make_float4(f4_dot(P0, zja), f4_dot(P1, zja), f4_dot(P2, zja), f4_dot(P3, zja));
    float4 tcol = make_float4(f4_dot(Zi0, u), f4_dot(Zi1, u), f4_dot(Zi2, u), f4_dot(Zi3, u));

    float4* o = reinterpret_cast<float4*>(out);
    size_t L4 = (size_t)L >> 2;
    size_t ij = (size_t)N * 4 + (size_t)e * 4 + a;
    size_t ji = ij + (size_t)E * 4;

    float rb = (float)(r * 4);
    float cb = (float)(c * 4);
    float ra = rb + (float)a;
    float ca = cb + (float)a;

    __stcs(o + ij,               make_float4(ra, ra, ra, ra));                   // rows ij
    __stcs(o + L4 + ij,          make_float4(cb, cb + 1.f, cb + 2.f, cb + 3.f)); // cols ij
    __stcs(o + 2 * L4 + ij,      clipneg(trow));                                 // vals ij
    __stcs(o + ji,               make_float4(ca, ca, ca, ca));                   // rows ji
    __stcs(o + L4 + ji,          make_float4(rb, rb + 1.f, rb + 2.f, rb + 3.f)); // cols ji
    __stcs(o + 2 * L4 + ji,      clipneg(tcol));                                 // vals ji
}

// ---------------------------------------------------------------------------
extern "C" void kernel_launch(void* const* d_in, const int* in_sizes, int n_in,
                              void* d_out, int out_size) {
    const float* maps = (const float*)d_in[0];
    const int*   ei   = (const int*)d_in[1];
    float*       out  = (float*)d_out;

    int twoE = in_sizes[0] / 16;           // 2E
    int E    = twoE / 2;
    long long L = (long long)out_size / 3; // entries per index array
    int N = (int)(L / 16 - twoE);

    int n4 = N * 4;
    int qe = E * 4;
    k_zero_diag<<<(n4 + 255) / 256, 256>>>(n4);
    k_edges<<<(qe + 255) / 256, 256>>>(maps, ei, E);
    k_nodes<<<(N + 127) / 128, 128>>>(out, N, L);
    k_emit <<<(qe + 255) / 256, 256>>>(out, ei, E, N, L);
}

// round 4
// speedup vs baseline: 1.9361x; 1.1401x over previous
#include <cuda_runtime.h>
#include <cstdint>

#define MAXN 50000
#define MAXE 800000

// Device scratch (allocation-free rule: __device__ globals)
__device__ float g_diag[(size_t)MAXN * 16];   // per-node Gram accumulators
__device__ float g_invs[(size_t)MAXN * 16];   // per-node inverse sqrt matrices
__device__ float g_triu[(size_t)MAXE * 16];   // per-edge M1^T M2

// float4 helpers
__device__ __forceinline__ float4 f4_fma(float s, float4 v, float4 acc) {
    acc.x = fmaf(s, v.x, acc.x); acc.y = fmaf(s, v.y, acc.y);
    acc.z = fmaf(s, v.z, acc.z); acc.w = fmaf(s, v.w, acc.w);
    return acc;
}
__device__ __forceinline__ float pick(float4 v, int a) {
    float r = v.x;
    r = (a == 1) ? v.y : r;
    r = (a == 2) ? v.z : r;
    r = (a == 3) ? v.w : r;
    return r;
}
__device__ __forceinline__ float4 shfl4(float4 v, int src) {
    float4 r;
    r.x = __shfl_sync(0xffffffffu, v.x, src, 4);
    r.y = __shfl_sync(0xffffffffu, v.y, src, 4);
    r.z = __shfl_sync(0xffffffffu, v.z, src, 4);
    r.w = __shfl_sync(0xffffffffu, v.w, src, 4);
    return r;
}
__device__ __forceinline__ float4 clip4(float4 v) {
    return make_float4(fminf(fmaxf(v.x, -1.f), 1.f),
                       fminf(fmaxf(v.y, -1.f), 1.f),
                       fminf(fmaxf(v.z, -1.f), 1.f),
                       fminf(fmaxf(v.w, -1.f), 1.f));
}
__device__ __forceinline__ float4 neg4(float4 v) {
    return make_float4(-v.x, -v.y, -v.z, -v.w);
}

// ---------------------------------------------------------------------------
// Kernel 0: zero the diag accumulators
// ---------------------------------------------------------------------------
__global__ void k_zero_diag(int n4) {
    int i = blockIdx.x * blockDim.x + threadIdx.x;
    if (i < n4) reinterpret_cast<float4*>(g_diag)[i] = make_float4(0.f, 0.f, 0.f, 0.f);
}

// ---------------------------------------------------------------------------
// Kernel 1 (quad-per-edge, shuffle-shared): thread (e, a) loads only row a of
// M1 and M2; other rows come via quad shuffles. Computes row a of
//   C1 = M1^T M1 -> atomicAdd diag[row];  C2 = M2^T M2 -> atomicAdd diag[col]
//   P  = M1^T M2 -> streaming store g_triu[e] row a
// ---------------------------------------------------------------------------
__global__ void k_edges(const float* __restrict__ maps,
                        const int*   __restrict__ ei0,
                        int E) {
    int t = blockIdx.x * blockDim.x + threadIdx.x;
    int e = t >> 2, a = t & 3;
    if (e >= E) return;

    const float4* mp = reinterpret_cast<const float4*>(maps);
    float4 m1row = __ldcs(mp + (size_t)e * 4 + a);
    float4 m2row = __ldcs(mp + ((size_t)E + e) * 4 + a);

    float4 c1 = make_float4(0.f, 0.f, 0.f, 0.f);
    float4 c2 = c1, p = c1;
#pragma unroll
    for (int k = 0; k < 4; k++) {
        float4 r1 = shfl4(m1row, k);     // M1 row k
        float4 r2 = shfl4(m2row, k);     // M2 row k
        float s1 = pick(r1, a);          // M1[k][a]
        float s2 = pick(r2, a);          // M2[k][a]
        c1 = f4_fma(s1, r1, c1);         // C1[a][:] += M1[k][a]*M1[k][:]
        c2 = f4_fma(s2, r2, c2);
        p  = f4_fma(s1, r2, p);          // P[a][:]  += M1[k][a]*M2[k][:]
    }

    int r = ei0[e];
    int c = ei0[E + e];

    atomicAdd(reinterpret_cast<float4*>(g_diag) + (size_t)r * 4 + a, c1);
    atomicAdd(reinterpret_cast<float4*>(g_diag) + (size_t)c * 4 + a, c2);
    __stcs(reinterpret_cast<float4*>(g_triu) + (size_t)e * 4 + a, p);
}

// 4x4 matmul helper (row-major [16])
__device__ __forceinline__ void mm4(const float* __restrict__ A,
                                    const float* __restrict__ B,
                                    float* __restrict__ C) {
#pragma unroll
    for (int i = 0; i < 4; i++) {
#pragma unroll
        for (int j = 0; j < 4; j++) {
            float s = A[i * 4 + 0] * B[0 * 4 + j];
            s += A[i * 4 + 1] * B[1 * 4 + j];
            s += A[i * 4 + 2] * B[2 * 4 + j];
            s += A[i * 4 + 3] * B[3 * 4 + j];
            C[i * 4 + j] = s;
        }
    }
}

// ---------------------------------------------------------------------------
// Kernel 2: per node n: Z = (diag+I)^{-1/2} via Newton-Schulz,
// store Z, emit diag block (rows, cols, vals).
// ---------------------------------------------------------------------------
__global__ void k_nodes(float* __restrict__ out, int N, long long L) {
    int n = blockIdx.x * blockDim.x + threadIdx.x;
    if (n >= N) return;

    float A0[16], A[16];
    const float4* dp = reinterpret_cast<const float4*>(&g_diag[(size_t)n * 16]);
#pragma unroll
    for (int q = 0; q < 4; q++) {
        float4 v = dp[q];
        A0[q * 4 + 0] = v.x; A0[q * 4 + 1] = v.y; A0[q * 4 + 2] = v.z; A0[q * 4 + 3] = v.w;
    }
#pragma unroll
    for (int i = 0; i < 16; i++) A[i] = A0[i];
    A[0] += 1.f; A[5] += 1.f; A[10] += 1.f; A[15] += 1.f;

    float tr = A[0] + A[5] + A[10] + A[15];
    float g = 0.f;
#pragma unroll
    for (int i = 0; i < 4; i++) {
        float rs = fabsf(A[i * 4 + 0]) + fabsf(A[i * 4 + 1]) +
                   fabsf(A[i * 4 + 2]) + fabsf(A[i * 4 + 3]);
        g = fmaxf(g, rs);
    }
    float s = fminf(tr, g);
    float inv_s = 1.f / s;

    float Y[16], Z[16];
#pragma unroll
    for (int i = 0; i < 16; i++) { Y[i] = A[i] * inv_s; Z[i] = 0.f; }
    Z[0] = Z[5] = Z[10] = Z[15] = 1.f;

#pragma unroll
    for (int it = 0; it < 14; it++) {
        float T[16], Yn[16], Zn[16];
        mm4(Z, Y, T);
#pragma unroll
        for (int i = 0; i < 16; i++) T[i] = -0.5f * T[i];
        T[0] += 1.5f; T[5] += 1.5f; T[10] += 1.5f; T[15] += 1.5f;
        mm4(Y, T, Yn);
        mm4(T, Z, Zn);
#pragma unroll
        for (int i = 0; i < 16; i++) { Y[i] = Yn[i]; Z[i] = Zn[i]; }
    }

    float rs = rsqrtf(s);
#pragma unroll
    for (int i = 0; i < 16; i++) Z[i] *= rs;

    float4* zp = reinterpret_cast<float4*>(&g_invs[(size_t)n * 16]);
#pragma unroll
    for (int q = 0; q < 4; q++)
        zp[q] = *reinterpret_cast<float4*>(&Z[q * 4]);

    float W[16], Dm[16];
    mm4(Z, A0, W);
    mm4(W, Z, Dm);
#pragma unroll
    for (int i = 0; i < 16; i++) Dm[i] = fminf(fmaxf(Dm[i], -1.f), 1.f);

    size_t base = (size_t)n * 16;
    float4* orow = reinterpret_cast<float4*>(out + base);
    float4* ocol = reinterpret_cast<float4*>(out + (size_t)L + base);
    float4* oval = reinterpret_cast<float4*>(out + 2 * (size_t)L + base);
    float nb = (float)(n * 4);
    float4 cv = make_float4(nb, nb + 1.f, nb + 2.f, nb + 3.f);
#pragma unroll
    for (int a = 0; a < 4; a++) {
        float rv = nb + (float)a;
        __stcs(orow + a, make_float4(rv, rv, rv, rv));
        __stcs(ocol + a, cv);
        __stcs(oval + a, *reinterpret_cast<float4*>(&Dm[a * 4]));
    }
}

// ---------------------------------------------------------------------------
// Kernel 3 (fused emit, quad-shuffle): thread (e, a) loads only row a of
// P, Zi, Zj. T row a = (Zi[a,:]·P)·Zj via shuffled rows; T^T row a obtained
// by a 4x4 quad transpose of the clipped trow. Emits all 6 output float4s.
// ---------------------------------------------------------------------------
__global__ void k_emit(float* __restrict__ out,
                       const int* __restrict__ ei0,
                       int E, int N, long long L) {
    int t = blockIdx.x * blockDim.x + threadIdx.x;
    int e = t >> 2, a = t & 3;
    if (e >= E) return;

    int r = ei0[e];
    int c = ei0[E + e];

    float4 Pa  = __ldcs(reinterpret_cast<const float4*>(g_triu) + (size_t)e * 4 + a);
    float4 zia = __ldg(reinterpret_cast<const float4*>(g_invs) + (size_t)r * 4 + a);
    float4 zja = __ldg(reinterpret_cast<const float4*>(g_invs) + (size_t)c * 4 + a);

    // w = Zi[a,:] * P   (needs all P rows via shuffle)
    float4 w = make_float4(0.f, 0.f, 0.f, 0.f);
    {
        float4 pk;
        pk = shfl4(Pa, 0); w = f4_fma(zia.x, pk, w);
        pk = shfl4(Pa, 1); w = f4_fma(zia.y, pk, w);
        pk = shfl4(Pa, 2); w = f4_fma(zia.z, pk, w);
        pk = shfl4(Pa, 3); w = f4_fma(zia.w, pk, w);
    }
    // trow = w * Zj   (needs all Zj rows via shuffle)
    float4 trow = make_float4(0.f, 0.f, 0.f, 0.f);
    {
        float4 zk;
        zk = shfl4(zja, 0); trow = f4_fma(w.x, zk, trow);
        zk = shfl4(zja, 1); trow = f4_fma(w.y, zk, trow);
        zk = shfl4(zja, 2); trow = f4_fma(w.z, zk, trow);
        zk = shfl4(zja, 3); trow = f4_fma(w.w, zk, trow);
    }
    float4 tc = clip4(trow);

    // tcol[j] = clipped T[j][a]: element a of thread j's tc (quad transpose)
    float4 tcol;
    tcol.x = pick(shfl4(tc, 0), a);
    tcol.y = pick(shfl4(tc, 1), a);
    tcol.z = pick(shfl4(tc, 2), a);
    tcol.w = pick(shfl4(tc, 3), a);

    float4* o = reinterpret_cast<float4*>(out);
    size_t L4 = (size_t)L >> 2;
    size_t ij = (size_t)N * 4 + (size_t)e * 4 + a;
    size_t ji = ij + (size_t)E * 4;

    float rb = (float)(r * 4);
    float cb = (float)(c * 4);
    float ra = rb + (float)a;
    float ca = cb + (float)a;

    __stcs(o + ij,          make_float4(ra, ra, ra, ra));                   // rows ij
    __stcs(o + L4 + ij,     make_float4(cb, cb + 1.f, cb + 2.f, cb + 3.f)); // cols ij
    __stcs(o + 2 * L4 + ij, neg4(tc));                                      // vals ij
    __stcs(o + ji,          make_float4(ca, ca, ca, ca));                   // rows ji
    __stcs(o + L4 + ji,     make_float4(rb, rb + 1.f, rb + 2.f, rb + 3.f)); // cols ji
    __stcs(o + 2 * L4 + ji, neg4(tcol));                                    // vals ji
}

// ---------------------------------------------------------------------------
extern "C" void kernel_launch(void* const* d_in, const int* in_sizes, int n_in,
                              void* d_out, int out_size) {
    const float* maps = (const float*)d_in[0];
    const int*   ei   = (const int*)d_in[1];
    float*       out  = (float*)d_out;

    int twoE = in_sizes[0] / 16;           // 2E
    int E    = twoE / 2;
    long long L = (long long)out_size / 3; // entries per index array
    int N = (int)(L / 16 - twoE);

    int n4 = N * 4;
    int qe = E * 4;
    k_zero_diag<<<(n4 + 255) / 256, 256>>>(n4);
    k_edges<<<(qe + 255) / 256, 256>>>(maps, ei, E);
    k_nodes<<<(N + 127) / 128, 128>>>(out, N, L);
    k_emit <<<(qe + 255) / 256, 256>>>(out, ei, E, N, L);
}